// round 11
// baseline (speedup 1.0000x reference)
#include <cuda_runtime.h>
#include <cuda_fp16.h>
#include <stdint.h>

// ============================================================================
// Problem constants (fixed per reference source)
// ============================================================================
#define K_DIM 4096
#define N_DIM 4096
#define M_MAX 8192
#define HASH_MASK 0xFFFFF        // HASH_SIZE = 2^20
#define P_CONST 56598313LL       // RzLinear.P (prime), hardcoded in reference

// Scratch (device globals; no allocation allowed)
// g_A: fragment-major fp16, [M/16][K/16][32 lanes][4 b32 words]; entry
//      (mt,k16,lane={lq*4+lr}) = m16n8k16 A-fragment.
// g_B: kt-major fp16, uint4 at index ((kt*4 + lr)*N + n), k0 = kt*32 + 2*lr:
//      .x=h2(w[k0],w[k0+1]) .y=h2(w[k0+8],w[k0+9])
//      .z=h2(w[k0+16],w[k0+17]) .w=h2(w[k0+24],w[k0+25])
//      (= B fragments for BOTH k16-steps of tile kt in one 16B load)
__device__ uint32_t g_A[(size_t)M_MAX * K_DIM / 2];
__device__ uint32_t g_B[(size_t)K_DIM * N_DIM / 2];
__device__ int      g_rowmod[K_DIM];              // (k*r3 + r1) % P
__device__ int      g_colmod[N_DIM];              // (n*r2) % P

__device__ __forceinline__ uint32_t pack_h2(float lo, float hi) {
    __half2 h = __floats2half2_rn(lo, hi);
    return *(uint32_t*)&h;
}
__device__ __forceinline__ uint32_t smem_u32(const void* p) {
    uint32_t a;
    asm("{ .reg .u64 t; cvta.to.shared.u64 t, %1; cvt.u32.u64 %0, t; }"
        : "=r"(a) : "l"(p));
    return a;
}
__device__ __forceinline__ void cp_async16(uint32_t dst, const void* src) {
    asm volatile("cp.async.cg.shared.global [%0], [%1], 16;"
                 :: "r"(dst), "l"(src) : "memory");
}
#define CP_COMMIT() asm volatile("cp.async.commit_group;" ::: "memory")
#define CP_WAIT2()  asm volatile("cp.async.wait_group 2;"  ::: "memory")
#define CP_WAIT0()  asm volatile("cp.async.wait_group 0;"  ::: "memory")

// m16n8k16 fp16 MMA, f32 accumulate (generic PTX, sm_80+)
__device__ __forceinline__ void mma_f16(float c[4], uint32_t a0, uint32_t a1,
                                        uint32_t a2, uint32_t a3,
                                        uint32_t b0, uint32_t b1) {
    asm volatile(
        "mma.sync.aligned.m16n8k16.row.col.f32.f16.f16.f32 "
        "{%0,%1,%2,%3}, {%4,%5,%6,%7}, {%8,%9}, {%0,%1,%2,%3};"
        : "+f"(c[0]), "+f"(c[1]), "+f"(c[2]), "+f"(c[3])
        : "r"(a0), "r"(a1), "r"(a2), "r"(a3), "r"(b0), "r"(b1));
}

// ============================================================================
// Kernel 1: hash residue tables (self-detects int64 vs int32 materialization)
// ============================================================================
__global__ void hash_tables_kernel(const void* __restrict__ rn_raw) {
    const long long* rn64 = (const long long*)rn_raw;
    const int*       rn32 = (const int*)rn_raw;
    long long r1, r2, r3;
    if (rn64[0] == P_CONST) { r1 = rn64[1]; r2 = rn64[2]; r3 = rn64[3]; }
    else                    { r1 = rn32[1]; r2 = rn32[2]; r3 = rn32[3]; }
    int i = blockIdx.x * blockDim.x + threadIdx.x;
    if (i < K_DIM) g_rowmod[i] = (int)(((long long)i * r3 + r1) % P_CONST);
    if (i < N_DIM) g_colmod[i] = (int)(((long long)i * r2) % P_CONST);
}

// ============================================================================
// Kernel 2: gather W into kt-major fp16 layout (8 lookups -> one uint4).
// ============================================================================
__global__ void gather_kernel(const float* __restrict__ hw) {
    const int P = (int)P_CONST;
    const int t = blockIdx.x * blockDim.x + threadIdx.x;
    const int total = (K_DIM / 8) * N_DIM;      // 2M uint4 entries
    if (t >= total) return;

    const int n  = t & (N_DIM - 1);
    const int r  = t >> 12;                     // kt*4 + lr
    const int lr = r & 3;
    const int k0 = (r >> 2) * 32 + 2 * lr;
    const int c  = g_colmod[n];

    float w[8];
    #pragma unroll
    for (int j = 0; j < 4; j++) {
        const int ka = k0 + j * 8;
        int s0 = g_rowmod[ka]     + c; if (s0 >= P) s0 -= P;
        int s1 = g_rowmod[ka + 1] + c; if (s1 >= P) s1 -= P;
        w[2 * j]     = __ldg(hw + (s0 & HASH_MASK));
        w[2 * j + 1] = __ldg(hw + (s1 & HASH_MASK));
    }

    uint4 o;
    o.x = pack_h2(w[0], w[1]);
    o.y = pack_h2(w[2], w[3]);
    o.z = pack_h2(w[4], w[5]);
    o.w = pack_h2(w[6], w[7]);
    ((uint4*)g_B)[t] = o;
}

// ============================================================================
// Kernel 3: x -> fp16, fragment-major permutation (unchanged, proven)
// ============================================================================
__global__ void cvt_a_kernel(const float* __restrict__ x, int total) {
    int t = blockIdx.x * blockDim.x + threadIdx.x;
    if (t >= total) return;
    const int lane = t & 31;
    const int k16  = (t >> 5) & (K_DIM / 16 - 1);
    const int mt   = t >> (5 + 8);            // K/16 = 256 -> 8 bits
    const int lq = lane >> 2, lr = lane & 3;
    const float* xm = x + (size_t)(mt * 16) * K_DIM + k16 * 16;
    const float2 p0 = *(const float2*)(xm + (size_t)lq * K_DIM + 2 * lr);
    const float2 p1 = *(const float2*)(xm + (size_t)(lq + 8) * K_DIM + 2 * lr);
    const float2 p2 = *(const float2*)(xm + (size_t)lq * K_DIM + 2 * lr + 8);
    const float2 p3 = *(const float2*)(xm + (size_t)(lq + 8) * K_DIM + 2 * lr + 8);
    uint4 o;
    o.x = pack_h2(p0.x, p0.y);
    o.y = pack_h2(p1.x, p1.y);
    o.z = pack_h2(p2.x, p2.y);
    o.w = pack_h2(p3.x, p3.y);
    ((uint4*)g_A)[t] = o;
}

// ============================================================================
// Kernel 4: fp16 tensor-core GEMM via mma.sync m16n8k16
//   CTA tile 128x256, BK=32 (2 k16-steps), 512 thr (16 warps 2x8 ->
//   warp tile 64x32), 4-stage cp.async pipeline, ONE __syncthreads per kt.
//   A fragments: 1x LDS.128 (fragment-major, conflict-free).
//   B fragments: 1x LDS.128 carrying BOTH ks-steps (held in regs whole kt);
//     row stride 4128B ≡ 32 mod 128 -> any 8 consecutive lanes hit 8
//     distinct 16B banks -> conflict-free.
//   Per warp per kt: 12 LDS vs 32 MMAs; ks1's A-loads hoist under ks0 MMAs.
// ============================================================================
#define RS_W 1032                                  // B smem row stride (words)
#define A_STAGE_B (8 * 2 * 32 * 16)                // 8192
#define B_STAGE_B (4 * RS_W * 4)                   // 16512
#define STAGE_B   (A_STAGE_B + B_STAGE_B)          // 24704
#define NSTAGE 4
#define SMEM_GEMM (NSTAGE * STAGE_B)               // 98816
#define NK        (K_DIM / 32)                     // 128

__device__ __forceinline__ void load_stage(uint32_t sbase, int stage,
                                           int m0, int n0, int kt, int tid) {
    const uint32_t a_s = sbase + stage * STAGE_B;
    const uint32_t b_s = a_s + A_STAGE_B;
    // A: 16 fragment-chunks of 512B; 512 x 16B transfers, 1 per thread.
    {
        const int chunk = tid >> 5;          // 0..15
        const int lane  = tid & 31;
        const int i = chunk >> 1;            // mtile within CTA
        const int j = chunk & 1;             // kstep
        const uint32_t* src = g_A +
            (((size_t)(m0 / 16 + i) * (K_DIM / 16) + (kt * 2 + j)) * 32
             + lane) * 4;
        cp_async16(a_s + tid * 16, src);
    }
    // B: 4 rows x 256 uint4; 1024 x 16B transfers, 2 per thread.
    #pragma unroll
    for (int p = 0; p < 2; p++) {
        const int u = tid + p * 512;
        const int r = u >> 8;                // 0..3
        const int c = u & 255;
        const uint32_t* src =
            g_B + ((size_t)(kt * 4 + r) * N_DIM + n0 + c) * 4;
        cp_async16(b_s + r * (RS_W * 4) + c * 16, src);
    }
}

__global__ __launch_bounds__(512, 1)
void gemm_mma_kernel(const float* __restrict__ bias, float* __restrict__ C) {
    extern __shared__ char smem[];
    const uint32_t sbase = smem_u32(smem);
    const int tid  = threadIdx.x;
    const int wid  = tid >> 5;
    const int lane = tid & 31;
    const int lq = lane >> 2;     // 0..7
    const int lr = lane & 3;      // 0..3
    const int wm = wid & 1;       // 2 m-halves of 64
    const int wn = wid >> 1;      // 8 n-slices of 32

    const int m_blk = blockIdx.y * 128;
    const int n_blk = blockIdx.x * 256;

    float acc[4][4][4];
    #pragma unroll
    for (int i = 0; i < 4; i++)
        #pragma unroll
        for (int j = 0; j < 4; j++)
            #pragma unroll
            for (int r = 0; r < 4; r++) acc[i][j][r] = 0.0f;

    load_stage(sbase, 0, m_blk, n_blk, 0, tid); CP_COMMIT();
    load_stage(sbase, 1, m_blk, n_blk, 1, tid); CP_COMMIT();
    load_stage(sbase, 2, m_blk, n_blk, 2, tid); CP_COMMIT();

    for (int kt = 0; kt < NK; kt++) {
        CP_WAIT2();
        __syncthreads();    // single barrier per kt (slot (kt-1)&3 drained)
        const int st = kt & (NSTAGE - 1);
        const uint32_t* As = (const uint32_t*)(smem + st * STAGE_B);
        const uint32_t* Bs = (const uint32_t*)(smem + st * STAGE_B + A_STAGE_B);

        const uint32_t* a_base = As + (wm * 8) * 128 + lane * 4;
        const uint32_t* b_base = Bs + lr * RS_W + (wn * 32 + lq) * 4;

        // B for BOTH ks-steps: 4x LDS.128, held in registers the whole kt
        uint4 b[4];
        #pragma unroll
        for (int jn = 0; jn < 4; jn++)
            b[jn] = *(const uint4*)(b_base + jn * 32);

        // ks0
        uint4 a0[4];
        #pragma unroll
        for (int im = 0; im < 4; im++)
            a0[im] = *(const uint4*)(a_base + (im * 2) * 128);
        // ks1 A-loads issued before ks0 MMAs so they overlap the burst
        uint4 a1[4];
        #pragma unroll
        for (int im = 0; im < 4; im++)
            a1[im] = *(const uint4*)(a_base + (im * 2 + 1) * 128);

        #pragma unroll
        for (int im = 0; im < 4; im++)
            #pragma unroll
            for (int jn = 0; jn < 4; jn++)
                mma_f16(acc[im][jn], a0[im].x, a0[im].y, a0[im].z, a0[im].w,
                        b[jn].x, b[jn].y);
        #pragma unroll
        for (int im = 0; im < 4; im++)
            #pragma unroll
            for (int jn = 0; jn < 4; jn++)
                mma_f16(acc[im][jn], a1[im].x, a1[im].y, a1[im].z, a1[im].w,
                        b[jn].z, b[jn].w);

        if (kt + 3 < NK)
            load_stage(sbase, (kt + 3) & (NSTAGE - 1), m_blk, n_blk,
                       kt + 3, tid);
        CP_COMMIT();   // keep group count in lockstep even when empty
    }
    CP_WAIT0();

    // epilogue: bias + direct stores
    #pragma unroll
    for (int jn = 0; jn < 4; jn++) {
        const int c0 = n_blk + wn * 32 + jn * 8 + 2 * lr;
        const float bx = __ldg(bias + c0);
        const float by = __ldg(bias + c0 + 1);
        #pragma unroll
        for (int im = 0; im < 4; im++) {
            const int r0 = m_blk + wm * 64 + im * 16 + lq;
            float2 v0, v1;
            v0.x = acc[im][jn][0] + bx; v0.y = acc[im][jn][1] + by;
            v1.x = acc[im][jn][2] + bx; v1.y = acc[im][jn][3] + by;
            *(float2*)(C + (size_t)r0 * N_DIM + c0)       = v0;
            *(float2*)(C + (size_t)(r0 + 8) * N_DIM + c0) = v1;
        }
    }
}

// ============================================================================
// Host launch. Inputs routed by element count (immune to metadata ordering):
//   <=8 elems -> random_numbers; 2^20 -> hashed_weight; 4096 -> bias;
//   largest -> x. Output f32 [M, N_DIM].
// ============================================================================
extern "C" void kernel_launch(void* const* d_in, const int* in_sizes, int n_in,
                              void* d_out, int out_size) {
    const float* x = nullptr; const float* hw = nullptr;
    const void* rn = nullptr; const float* bias = nullptr;
    long long max_sz = -1; int max_i = 0;
    for (int i = 0; i < n_in; i++)
        if ((long long)in_sizes[i] > max_sz) { max_sz = in_sizes[i]; max_i = i; }
    x = (const float*)d_in[max_i];
    for (int i = 0; i < n_in; i++) {
        if (i == max_i) continue;
        if (in_sizes[i] <= 8)              rn   = d_in[i];
        else if (in_sizes[i] == (1 << 20)) hw   = (const float*)d_in[i];
        else if (in_sizes[i] == N_DIM)     bias = (const float*)d_in[i];
    }
    float* out = (float*)d_out;
    const int M = (int)(max_sz / K_DIM);   // 8192

    hash_tables_kernel<<<(K_DIM + 255) / 256, 256>>>(rn);

    const int a_total = (M / 16) * (K_DIM / 16) * 32;
    cvt_a_kernel<<<(a_total + 255) / 256, 256>>>(x, a_total);

    const int gtotal = (K_DIM / 8) * N_DIM;
    gather_kernel<<<(gtotal + 255) / 256, 256>>>(hw);

    static bool smem_set = false;
    if (!smem_set) {
        cudaFuncSetAttribute(gemm_mma_kernel,
                             cudaFuncAttributeMaxDynamicSharedMemorySize,
                             SMEM_GEMM);
        smem_set = true;
    }
    dim3 grid(N_DIM / 256, M / 128);
    gemm_mma_kernel<<<grid, 512, SMEM_GEMM>>>(bias, out);
}

// round 12
// speedup vs baseline: 1.0948x; 1.0948x over previous
#include <cuda_runtime.h>
#include <cuda_fp16.h>
#include <stdint.h>

// ============================================================================
// Problem constants (fixed per reference source)
// ============================================================================
#define K_DIM 4096
#define N_DIM 4096
#define M_MAX 8192
#define HASH_MASK 0xFFFFF        // HASH_SIZE = 2^20
#define P_CONST 56598313LL       // RzLinear.P (prime), hardcoded in reference

// Scratch (device globals; no allocation allowed)
// g_A: fragment-major fp16, [M/16][K/16][32 lanes][4 b32 words]; entry
//      (mt,k16,lane={lq*4+lr}) = m16n8k16 A-fragment.
// g_B: pair-major fp16, uint2 index r*N+n with r = k16*4 + lr:
//      .x = half2(w[k0,n], w[k0+1,n]), .y = half2(w[k0+8,n], w[k0+9,n]),
//      k0 = k16*16 + 2*lr.
__device__ uint32_t g_A[(size_t)M_MAX * K_DIM / 2];
__device__ uint32_t g_B[(size_t)K_DIM * N_DIM / 2];
__device__ int      g_rowmod[K_DIM];              // (k*r3 + r1) % P
__device__ int      g_colmod[N_DIM];              // (n*r2) % P

__device__ __forceinline__ uint32_t pack_h2(float lo, float hi) {
    __half2 h = __floats2half2_rn(lo, hi);
    return *(uint32_t*)&h;
}
__device__ __forceinline__ uint32_t smem_u32(const void* p) {
    uint32_t a;
    asm("{ .reg .u64 t; cvta.to.shared.u64 t, %1; cvt.u32.u64 %0, t; }"
        : "=r"(a) : "l"(p));
    return a;
}
__device__ __forceinline__ void cp_async16(uint32_t dst, const void* src) {
    asm volatile("cp.async.cg.shared.global [%0], [%1], 16;"
                 :: "r"(dst), "l"(src) : "memory");
}
#define CP_COMMIT() asm volatile("cp.async.commit_group;" ::: "memory")
#define CP_WAIT1()  asm volatile("cp.async.wait_group 1;"  ::: "memory")
#define CP_WAIT0()  asm volatile("cp.async.wait_group 0;"  ::: "memory")

// m16n8k16 fp16 MMA, f32 accumulate (generic PTX, sm_80+)
__device__ __forceinline__ void mma_f16(float c[4], uint32_t a0, uint32_t a1,
                                        uint32_t a2, uint32_t a3,
                                        uint32_t b0, uint32_t b1) {
    asm volatile(
        "mma.sync.aligned.m16n8k16.row.col.f32.f16.f16.f32 "
        "{%0,%1,%2,%3}, {%4,%5,%6,%7}, {%8,%9}, {%0,%1,%2,%3};"
        : "+f"(c[0]), "+f"(c[1]), "+f"(c[2]), "+f"(c[3])
        : "r"(a0), "r"(a1), "r"(a2), "r"(a3), "r"(b0), "r"(b1));
}

// ============================================================================
// Kernel 1: hash residue tables (self-detects int64 vs int32 materialization)
// ============================================================================
__global__ void hash_tables_kernel(const void* __restrict__ rn_raw) {
    const long long* rn64 = (const long long*)rn_raw;
    const int*       rn32 = (const int*)rn_raw;
    long long r1, r2, r3;
    if (rn64[0] == P_CONST) { r1 = rn64[1]; r2 = rn64[2]; r3 = rn64[3]; }
    else                    { r1 = rn32[1]; r2 = rn32[2]; r3 = rn32[3]; }
    int i = blockIdx.x * blockDim.x + threadIdx.x;
    if (i < K_DIM) g_rowmod[i] = (int)(((long long)i * r3 + r1) % P_CONST);
    if (i < N_DIM) g_colmod[i] = (int)(((long long)i * r2) % P_CONST);
}

// ============================================================================
// Kernel 2: gather W into pair-major fp16 layout (R10 layout, proven).
// ============================================================================
__global__ void gather_kernel(const float* __restrict__ hw) {
    const int P = (int)P_CONST;
    const int t = blockIdx.x * blockDim.x + threadIdx.x;
    const int total = (K_DIM / 4) * N_DIM;      // uint2 entries
    if (t >= total) return;

    const int n  = t & (N_DIM - 1);
    const int r  = t >> 12;                     // k16*4 + lr
    const int lr = r & 3;
    const int k0 = (r >> 2) * 16 + 2 * lr;

    const int rm0 = g_rowmod[k0];
    const int rm1 = g_rowmod[k0 + 1];
    const int rm2 = g_rowmod[k0 + 8];
    const int rm3 = g_rowmod[k0 + 9];
    const int c   = g_colmod[n];

    int s0 = rm0 + c; if (s0 >= P) s0 -= P;
    int s1 = rm1 + c; if (s1 >= P) s1 -= P;
    int s2 = rm2 + c; if (s2 >= P) s2 -= P;
    int s3 = rm3 + c; if (s3 >= P) s3 -= P;

    const float w0 = __ldg(hw + (s0 & HASH_MASK));
    const float w1 = __ldg(hw + (s1 & HASH_MASK));
    const float w2 = __ldg(hw + (s2 & HASH_MASK));
    const float w3 = __ldg(hw + (s3 & HASH_MASK));

    uint2 o;
    o.x = pack_h2(w0, w1);
    o.y = pack_h2(w2, w3);
    ((uint2*)g_B)[t] = o;
}

// ============================================================================
// Kernel 3: x -> fp16, fragment-major permutation (unchanged, proven)
// ============================================================================
__global__ void cvt_a_kernel(const float* __restrict__ x, int total) {
    int t = blockIdx.x * blockDim.x + threadIdx.x;
    if (t >= total) return;
    const int lane = t & 31;
    const int k16  = (t >> 5) & (K_DIM / 16 - 1);
    const int mt   = t >> (5 + 8);            // K/16 = 256 -> 8 bits
    const int lq = lane >> 2, lr = lane & 3;
    const float* xm = x + (size_t)(mt * 16) * K_DIM + k16 * 16;
    const float2 p0 = *(const float2*)(xm + (size_t)lq * K_DIM + 2 * lr);
    const float2 p1 = *(const float2*)(xm + (size_t)(lq + 8) * K_DIM + 2 * lr);
    const float2 p2 = *(const float2*)(xm + (size_t)lq * K_DIM + 2 * lr + 8);
    const float2 p3 = *(const float2*)(xm + (size_t)(lq + 8) * K_DIM + 2 * lr + 8);
    uint4 o;
    o.x = pack_h2(p0.x, p0.y);
    o.y = pack_h2(p1.x, p1.y);
    o.z = pack_h2(p2.x, p2.y);
    o.w = pack_h2(p3.x, p3.y);
    ((uint4*)g_A)[t] = o;
}

// ============================================================================
// Kernel 4: fp16 tensor-core GEMM via mma.sync m16n8k16
//   CTA tile 128x256, STAGE = 64 k (4 k16-steps), 512 thr (16 warps 2x8 ->
//   warp tile 64x32), 3-stage cp.async pipeline.
//   ONE __syncthreads per 64 k (half the barrier/lockstep events of R10);
//   the 4 ks-steps inside a stage have no barrier between them, so ks(i+1)
//   fragment loads overlap ks(i)'s 16-MMA burst freely.
//   A fragments: 1x LDS.128 (fragment-major, conflict-free).
//   B fragments: 1x LDS.64 (pair-major, SB_W=520 ≡ 8 mod 32 words).
// ============================================================================
#define SB_W 520
#define A_STAGE_B (8 * 4 * 32 * 16)                // 16384 (8 mtiles x 4 ks)
#define B_STAGE_B (16 * SB_W * 4)                  // 33280 (16 rows)
#define STAGE_B   (A_STAGE_B + B_STAGE_B)          // 49664
#define NSTAGE 3
#define SMEM_GEMM (NSTAGE * STAGE_B)               // 148992
#define NK64      (K_DIM / 64)                     // 64 stages of work

__device__ __forceinline__ void load_stage(uint32_t sbase, int stage,
                                           int m0, int n0, int kt, int tid) {
    const uint32_t a_s = sbase + stage * STAGE_B;
    const uint32_t b_s = a_s + A_STAGE_B;
    // A: 32 fragment-chunks of 512B (i = mtile 0..7, j = ks 0..3);
    //    1024 x 16B transfers, 2 per thread; gmem chunk contiguous.
    #pragma unroll
    for (int p = 0; p < 2; p++) {
        const int u     = tid + p * 512;
        const int chunk = u >> 5;            // 0..31
        const int lane  = u & 31;
        const int i = chunk >> 2;            // mtile within CTA
        const int j = chunk & 3;             // ks
        const uint32_t* src = g_A +
            (((size_t)(m0 / 16 + i) * (K_DIM / 16) + (kt * 4 + j)) * 32
             + lane) * 4;
        cp_async16(a_s + u * 16, src);
    }
    // B: 16 rows x 512 words (128 x 16B chunks per row); 4 per thread.
    #pragma unroll
    for (int p = 0; p < 4; p++) {
        const int u = tid + p * 512;
        const int r = u >> 7;                // 0..15
        const int c = u & 127;
        const uint32_t* src =
            g_B + ((size_t)(kt * 16 + r) * N_DIM + n0) * 2 + c * 4;
        cp_async16(b_s + r * (SB_W * 4) + c * 16, src);
    }
}

__global__ __launch_bounds__(512, 1)
void gemm_mma_kernel(const float* __restrict__ bias, float* __restrict__ C) {
    extern __shared__ char smem[];
    const uint32_t sbase = smem_u32(smem);
    const int tid  = threadIdx.x;
    const int wid  = tid >> 5;
    const int lane = tid & 31;
    const int lq = lane >> 2;     // 0..7
    const int lr = lane & 3;      // 0..3
    const int wm = wid & 1;       // 2 m-halves of 64
    const int wn = wid >> 1;      // 8 n-slices of 32

    const int m_blk = blockIdx.y * 128;
    const int n_blk = blockIdx.x * 256;

    float acc[4][4][4];
    #pragma unroll
    for (int i = 0; i < 4; i++)
        #pragma unroll
        for (int j = 0; j < 4; j++)
            #pragma unroll
            for (int r = 0; r < 4; r++) acc[i][j][r] = 0.0f;

    load_stage(sbase, 0, m_blk, n_blk, 0, tid); CP_COMMIT();
    load_stage(sbase, 1, m_blk, n_blk, 1, tid); CP_COMMIT();

    int st = 0;
    for (int kt = 0; kt < NK64; kt++) {
        CP_WAIT1();
        __syncthreads();    // single barrier per 64 k: the slot written at
                            // the end of iter t is (t+2)%3 = (t-1)%3, whose
                            // readers all passed this barrier already.
        const uint32_t* As = (const uint32_t*)(smem + st * STAGE_B);
        const uint32_t* Bs = (const uint32_t*)(smem + st * STAGE_B + A_STAGE_B);

        const uint32_t* a_base = As + (wm * 16) * 128 + lane * 4;
        const uint32_t* b_base = Bs + (wn * 32 + lq) * 2;

        #pragma unroll
        for (int ks = 0; ks < 4; ks++) {
            uint4 a[4];
            #pragma unroll
            for (int im = 0; im < 4; im++)
                a[im] = *(const uint4*)(a_base + (im * 4 + ks) * 128);
            uint2 b[4];
            #pragma unroll
            for (int jn = 0; jn < 4; jn++)
                b[jn] = *(const uint2*)
                    (b_base + (ks * 4 + lr) * SB_W + jn * 16);
            #pragma unroll
            for (int im = 0; im < 4; im++)
                #pragma unroll
                for (int jn = 0; jn < 4; jn++)
                    mma_f16(acc[im][jn], a[im].x, a[im].y, a[im].z, a[im].w,
                            b[jn].x, b[jn].y);
        }

        if (kt + 2 < NK64) {
            int ws = st + 2; if (ws >= NSTAGE) ws -= NSTAGE;
            load_stage(sbase, ws, m_blk, n_blk, kt + 2, tid);
        }
        CP_COMMIT();   // keep group count in lockstep even when empty
        st = (st == NSTAGE - 1) ? 0 : st + 1;
    }
    CP_WAIT0();

    // epilogue: bias + direct stores
    #pragma unroll
    for (int jn = 0; jn < 4; jn++) {
        const int c0 = n_blk + wn * 32 + jn * 8 + 2 * lr;
        const float bx = __ldg(bias + c0);
        const float by = __ldg(bias + c0 + 1);
        #pragma unroll
        for (int im = 0; im < 4; im++) {
            const int r0 = m_blk + wm * 64 + im * 16 + lq;
            float2 v0, v1;
            v0.x = acc[im][jn][0] + bx; v0.y = acc[im][jn][1] + by;
            v1.x = acc[im][jn][2] + bx; v1.y = acc[im][jn][3] + by;
            *(float2*)(C + (size_t)r0 * N_DIM + c0)       = v0;
            *(float2*)(C + (size_t)(r0 + 8) * N_DIM + c0) = v1;
        }
    }
}

// ============================================================================
// Host launch. Inputs routed by element count (immune to metadata ordering):
//   <=8 elems -> random_numbers; 2^20 -> hashed_weight; 4096 -> bias;
//   largest -> x. Output f32 [M, N_DIM].
// ============================================================================
extern "C" void kernel_launch(void* const* d_in, const int* in_sizes, int n_in,
                              void* d_out, int out_size) {
    const float* x = nullptr; const float* hw = nullptr;
    const void* rn = nullptr; const float* bias = nullptr;
    long long max_sz = -1; int max_i = 0;
    for (int i = 0; i < n_in; i++)
        if ((long long)in_sizes[i] > max_sz) { max_sz = in_sizes[i]; max_i = i; }
    x = (const float*)d_in[max_i];
    for (int i = 0; i < n_in; i++) {
        if (i == max_i) continue;
        if (in_sizes[i] <= 8)              rn   = d_in[i];
        else if (in_sizes[i] == (1 << 20)) hw   = (const float*)d_in[i];
        else if (in_sizes[i] == N_DIM)     bias = (const float*)d_in[i];
    }
    float* out = (float*)d_out;
    const int M = (int)(max_sz / K_DIM);   // 8192

    hash_tables_kernel<<<(K_DIM + 255) / 256, 256>>>(rn);

    const int a_total = (M / 16) * (K_DIM / 16) * 32;
    cvt_a_kernel<<<(a_total + 255) / 256, 256>>>(x, a_total);

    const int gtotal = (K_DIM / 4) * N_DIM;
    gather_kernel<<<(gtotal + 255) / 256, 256>>>(hw);

    static bool smem_set = false;
    if (!smem_set) {
        cudaFuncSetAttribute(gemm_mma_kernel,
                             cudaFuncAttributeMaxDynamicSharedMemorySize,
                             SMEM_GEMM);
        smem_set = true;
    }
    dim3 grid(N_DIM / 256, M / 128);
    gemm_mma_kernel<<<grid, 512, SMEM_GEMM>>>(bias, out);
}

// round 13
// speedup vs baseline: 1.1061x; 1.0104x over previous
#include <cuda_runtime.h>
#include <cuda_fp16.h>
#include <stdint.h>

// ============================================================================
// Problem constants (fixed per reference source)
// ============================================================================
#define K_DIM 4096
#define N_DIM 4096
#define M_MAX 8192
#define HASH_MASK 0xFFFFF        // HASH_SIZE = 2^20
#define P_CONST 56598313LL       // RzLinear.P (prime), hardcoded in reference

// Scratch (device globals; no allocation allowed)
// g_A: fragment-major fp16, [M/16][K/16][32 lanes][4 b32 words]; entry
//      (mt,k16,lane={lq*4+lr}) = m16n8k16 A-fragment.
// g_B: pair-major fp16, uint2 index r*N+n with r = k16*4 + lr:
//      .x = half2(w[k0,n], w[k0+1,n]), .y = half2(w[k0+8,n], w[k0+9,n]),
//      k0 = k16*16 + 2*lr.
__device__ uint32_t g_A[(size_t)M_MAX * K_DIM / 2];
__device__ uint32_t g_B[(size_t)K_DIM * N_DIM / 2];
__device__ int      g_rowmod[K_DIM];              // (k*r3 + r1) % P
__device__ int      g_colmod[N_DIM];              // (n*r2) % P

__device__ __forceinline__ uint32_t pack_h2(float lo, float hi) {
    __half2 h = __floats2half2_rn(lo, hi);
    return *(uint32_t*)&h;
}
__device__ __forceinline__ uint32_t smem_u32(const void* p) {
    uint32_t a;
    asm("{ .reg .u64 t; cvta.to.shared.u64 t, %1; cvt.u32.u64 %0, t; }"
        : "=r"(a) : "l"(p));
    return a;
}
__device__ __forceinline__ void cp_async16(uint32_t dst, const void* src) {
    asm volatile("cp.async.cg.shared.global [%0], [%1], 16;"
                 :: "r"(dst), "l"(src) : "memory");
}
#define CP_COMMIT() asm volatile("cp.async.commit_group;" ::: "memory")
#define CP_WAIT2()  asm volatile("cp.async.wait_group 2;"  ::: "memory")
#define CP_WAIT0()  asm volatile("cp.async.wait_group 0;"  ::: "memory")

// m16n8k16 fp16 MMA, f32 accumulate (generic PTX, sm_80+)
__device__ __forceinline__ void mma_f16(float c[4], uint32_t a0, uint32_t a1,
                                        uint32_t a2, uint32_t a3,
                                        uint32_t b0, uint32_t b1) {
    asm volatile(
        "mma.sync.aligned.m16n8k16.row.col.f32.f16.f16.f32 "
        "{%0,%1,%2,%3}, {%4,%5,%6,%7}, {%8,%9}, {%0,%1,%2,%3};"
        : "+f"(c[0]), "+f"(c[1]), "+f"(c[2]), "+f"(c[3])
        : "r"(a0), "r"(a1), "r"(a2), "r"(a3), "r"(b0), "r"(b1));
}

// ============================================================================
// Kernel 1: hash residue tables (self-detects int64 vs int32 materialization)
// ============================================================================
__global__ void hash_tables_kernel(const void* __restrict__ rn_raw) {
    const long long* rn64 = (const long long*)rn_raw;
    const int*       rn32 = (const int*)rn_raw;
    long long r1, r2, r3;
    if (rn64[0] == P_CONST) { r1 = rn64[1]; r2 = rn64[2]; r3 = rn64[3]; }
    else                    { r1 = rn32[1]; r2 = rn32[2]; r3 = rn32[3]; }
    int i = blockIdx.x * blockDim.x + threadIdx.x;
    if (i < K_DIM) g_rowmod[i] = (int)(((long long)i * r3 + r1) % P_CONST);
    if (i < N_DIM) g_colmod[i] = (int)(((long long)i * r2) % P_CONST);
}

// ============================================================================
// Kernel 2: gather W into pair-major fp16 layout (proven).
// ============================================================================
__global__ void gather_kernel(const float* __restrict__ hw) {
    const int P = (int)P_CONST;
    const int t = blockIdx.x * blockDim.x + threadIdx.x;
    const int total = (K_DIM / 4) * N_DIM;      // uint2 entries
    if (t >= total) return;

    const int n  = t & (N_DIM - 1);
    const int r  = t >> 12;                     // k16*4 + lr
    const int lr = r & 3;
    const int k0 = (r >> 2) * 16 + 2 * lr;

    const int rm0 = g_rowmod[k0];
    const int rm1 = g_rowmod[k0 + 1];
    const int rm2 = g_rowmod[k0 + 8];
    const int rm3 = g_rowmod[k0 + 9];
    const int c   = g_colmod[n];

    int s0 = rm0 + c; if (s0 >= P) s0 -= P;
    int s1 = rm1 + c; if (s1 >= P) s1 -= P;
    int s2 = rm2 + c; if (s2 >= P) s2 -= P;
    int s3 = rm3 + c; if (s3 >= P) s3 -= P;

    const float w0 = __ldg(hw + (s0 & HASH_MASK));
    const float w1 = __ldg(hw + (s1 & HASH_MASK));
    const float w2 = __ldg(hw + (s2 & HASH_MASK));
    const float w3 = __ldg(hw + (s3 & HASH_MASK));

    uint2 o;
    o.x = pack_h2(w0, w1);
    o.y = pack_h2(w2, w3);
    ((uint2*)g_B)[t] = o;
}

// ============================================================================
// Kernel 3: x -> fp16, fragment-major permutation (proven)
// ============================================================================
__global__ void cvt_a_kernel(const float* __restrict__ x, int total) {
    int t = blockIdx.x * blockDim.x + threadIdx.x;
    if (t >= total) return;
    const int lane = t & 31;
    const int k16  = (t >> 5) & (K_DIM / 16 - 1);
    const int mt   = t >> (5 + 8);            // K/16 = 256 -> 8 bits
    const int lq = lane >> 2, lr = lane & 3;
    const float* xm = x + (size_t)(mt * 16) * K_DIM + k16 * 16;
    const float2 p0 = *(const float2*)(xm + (size_t)lq * K_DIM + 2 * lr);
    const float2 p1 = *(const float2*)(xm + (size_t)(lq + 8) * K_DIM + 2 * lr);
    const float2 p2 = *(const float2*)(xm + (size_t)lq * K_DIM + 2 * lr + 8);
    const float2 p3 = *(const float2*)(xm + (size_t)(lq + 8) * K_DIM + 2 * lr + 8);
    uint4 o;
    o.x = pack_h2(p0.x, p0.y);
    o.y = pack_h2(p1.x, p1.y);
    o.z = pack_h2(p2.x, p2.y);
    o.w = pack_h2(p3.x, p3.y);
    ((uint4*)g_A)[t] = o;
}

// ============================================================================
// Kernel 4: fp16 tensor-core GEMM via mma.sync m16n8k16
//   CTA tile 128x256, STAGE = 64 k (4 k16-steps), 512 thr (16 warps 2x8 ->
//   warp tile 64x32), 4-stage cp.async pipeline, ONE barrier per 64 k.
//   NEW: per-warp ks-phase rotation — warp wn computes ks in order
//   (ks_i + wn) & 3, so at any instant ~1/4 of warps are in their LDS
//   phase and ~3/4 in MMA phase: crossbar and tensor pipes run
//   concurrently instead of alternating in post-barrier lockstep.
//   A fragments: 1x LDS.128 (fragment-major, conflict-free).
//   B fragments: 1x LDS.64 (pair-major, SB_W=520 ≡ 8 mod 32 words).
// ============================================================================
#define SB_W 520
#define A_STAGE_B (8 * 4 * 32 * 16)                // 16384 (8 mtiles x 4 ks)
#define B_STAGE_B (16 * SB_W * 4)                  // 33280 (16 rows)
#define STAGE_B   (A_STAGE_B + B_STAGE_B)          // 49664
#define NSTAGE 4
#define SMEM_GEMM (NSTAGE * STAGE_B)               // 198656
#define NK64      (K_DIM / 64)                     // 64 stages of work

__device__ __forceinline__ void load_stage(uint32_t sbase, int stage,
                                           int m0, int n0, int kt, int tid) {
    const uint32_t a_s = sbase + stage * STAGE_B;
    const uint32_t b_s = a_s + A_STAGE_B;
    // A: 32 fragment-chunks of 512B (i = mtile 0..7, j = ks 0..3);
    //    1024 x 16B transfers, 2 per thread; gmem chunk contiguous.
    #pragma unroll
    for (int p = 0; p < 2; p++) {
        const int u     = tid + p * 512;
        const int chunk = u >> 5;            // 0..31
        const int lane  = u & 31;
        const int i = chunk >> 2;            // mtile within CTA
        const int j = chunk & 3;             // ks
        const uint32_t* src = g_A +
            (((size_t)(m0 / 16 + i) * (K_DIM / 16) + (kt * 4 + j)) * 32
             + lane) * 4;
        cp_async16(a_s + u * 16, src);
    }
    // B: 16 rows x 512 words (128 x 16B chunks per row); 4 per thread.
    #pragma unroll
    for (int p = 0; p < 4; p++) {
        const int u = tid + p * 512;
        const int r = u >> 7;                // 0..15
        const int c = u & 127;
        const uint32_t* src =
            g_B + ((size_t)(kt * 16 + r) * N_DIM + n0) * 2 + c * 4;
        cp_async16(b_s + r * (SB_W * 4) + c * 16, src);
    }
}

__global__ __launch_bounds__(512, 1)
void gemm_mma_kernel(const float* __restrict__ bias, float* __restrict__ C) {
    extern __shared__ char smem[];
    const uint32_t sbase = smem_u32(smem);
    const int tid  = threadIdx.x;
    const int wid  = tid >> 5;
    const int lane = tid & 31;
    const int lq = lane >> 2;     // 0..7
    const int lr = lane & 3;      // 0..3
    const int wm = wid & 1;       // 2 m-halves of 64
    const int wn = wid >> 1;      // 8 n-slices of 32
    const int rot = wn & 3;       // per-warp ks phase offset

    const int m_blk = blockIdx.y * 128;
    const int n_blk = blockIdx.x * 256;

    float acc[4][4][4];
    #pragma unroll
    for (int i = 0; i < 4; i++)
        #pragma unroll
        for (int j = 0; j < 4; j++)
            #pragma unroll
            for (int r = 0; r < 4; r++) acc[i][j][r] = 0.0f;

    load_stage(sbase, 0, m_blk, n_blk, 0, tid); CP_COMMIT();
    load_stage(sbase, 1, m_blk, n_blk, 1, tid); CP_COMMIT();
    load_stage(sbase, 2, m_blk, n_blk, 2, tid); CP_COMMIT();

    for (int kt = 0; kt < NK64; kt++) {
        CP_WAIT2();
        __syncthreads();    // single barrier per 64 k: slot written at iter
                            // kt is (kt+3)&3 = (kt-1)&3, whose readers all
                            // passed this barrier already.
        const int st = kt & (NSTAGE - 1);
        const uint32_t* As = (const uint32_t*)(smem + st * STAGE_B);
        const uint32_t* Bs = (const uint32_t*)(smem + st * STAGE_B + A_STAGE_B);

        const uint32_t* a_base = As + (wm * 16) * 128 + lane * 4;
        const uint32_t* b_base = Bs + (wn * 32 + lq) * 2;

        #pragma unroll
        for (int ks_i = 0; ks_i < 4; ks_i++) {
            const int ks = (ks_i + rot) & 3;   // phase-skewed step order
            uint4 a[4];
            #pragma unroll
            for (int im = 0; im < 4; im++)
                a[im] = *(const uint4*)(a_base + (im * 4 + ks) * 128);
            uint2 b[4];
            #pragma unroll
            for (int jn = 0; jn < 4; jn++)
                b[jn] = *(const uint2*)
                    (b_base + (ks * 4 + lr) * SB_W + jn * 16);
            #pragma unroll
            for (int im = 0; im < 4; im++)
                #pragma unroll
                for (int jn = 0; jn < 4; jn++)
                    mma_f16(acc[im][jn], a[im].x, a[im].y, a[im].z, a[im].w,
                            b[jn].x, b[jn].y);
        }

        if (kt + 3 < NK64)
            load_stage(sbase, (kt + 3) & (NSTAGE - 1), m_blk, n_blk,
                       kt + 3, tid);
        CP_COMMIT();   // keep group count in lockstep even when empty
    }
    CP_WAIT0();

    // epilogue: bias + direct stores
    #pragma unroll
    for (int jn = 0; jn < 4; jn++) {
        const int c0 = n_blk + wn * 32 + jn * 8 + 2 * lr;
        const float bx = __ldg(bias + c0);
        const float by = __ldg(bias + c0 + 1);
        #pragma unroll
        for (int im = 0; im < 4; im++) {
            const int r0 = m_blk + wm * 64 + im * 16 + lq;
            float2 v0, v1;
            v0.x = acc[im][jn][0] + bx; v0.y = acc[im][jn][1] + by;
            v1.x = acc[im][jn][2] + bx; v1.y = acc[im][jn][3] + by;
            *(float2*)(C + (size_t)r0 * N_DIM + c0)       = v0;
            *(float2*)(C + (size_t)(r0 + 8) * N_DIM + c0) = v1;
        }
    }
}

// ============================================================================
// Host launch. Inputs routed by element count (immune to metadata ordering):
//   <=8 elems -> random_numbers; 2^20 -> hashed_weight; 4096 -> bias;
//   largest -> x. Output f32 [M, N_DIM].
// ============================================================================
extern "C" void kernel_launch(void* const* d_in, const int* in_sizes, int n_in,
                              void* d_out, int out_size) {
    const float* x = nullptr; const float* hw = nullptr;
    const void* rn = nullptr; const float* bias = nullptr;
    long long max_sz = -1; int max_i = 0;
    for (int i = 0; i < n_in; i++)
        if ((long long)in_sizes[i] > max_sz) { max_sz = in_sizes[i]; max_i = i; }
    x = (const float*)d_in[max_i];
    for (int i = 0; i < n_in; i++) {
        if (i == max_i) continue;
        if (in_sizes[i] <= 8)              rn   = d_in[i];
        else if (in_sizes[i] == (1 << 20)) hw   = (const float*)d_in[i];
        else if (in_sizes[i] == N_DIM)     bias = (const float*)d_in[i];
    }
    float* out = (float*)d_out;
    const int M = (int)(max_sz / K_DIM);   // 8192

    hash_tables_kernel<<<(K_DIM + 255) / 256, 256>>>(rn);

    const int a_total = (M / 16) * (K_DIM / 16) * 32;
    cvt_a_kernel<<<(a_total + 255) / 256, 256>>>(x, a_total);

    const int gtotal = (K_DIM / 4) * N_DIM;
    gather_kernel<<<(gtotal + 255) / 256, 256>>>(hw);

    static bool smem_set = false;
    if (!smem_set) {
        cudaFuncSetAttribute(gemm_mma_kernel,
                             cudaFuncAttributeMaxDynamicSharedMemorySize,
                             SMEM_GEMM);
        smem_set = true;
    }
    dim3 grid(N_DIM / 256, M / 128);
    gemm_mma_kernel<<<grid, 512, SMEM_GEMM>>>(bias, out);
}

// round 14
// speedup vs baseline: 1.1829x; 1.0694x over previous
#include <cuda_runtime.h>
#include <cuda_fp16.h>
#include <stdint.h>

// ============================================================================
// Problem constants (fixed per reference source)
// ============================================================================
#define K_DIM 4096
#define N_DIM 4096
#define M_MAX 8192
#define HASH_MASK 0xFFFFF        // HASH_SIZE = 2^20
#define P_CONST 56598313LL       // RzLinear.P (prime), hardcoded in reference

// Scratch (device globals; no allocation allowed)
// g_A: fragment-major fp16, [M/16][K/16][32 lanes][4 b32 words]; entry
//      (mt,k16,lane={lq*4+lr}) = m16n8k16 A-fragment.
// g_B: pair-major fp16, uint2 index r*N+n with r = k16*4 + lr:
//      .x = half2(w[k0,n], w[k0+1,n]), .y = half2(w[k0+8,n], w[k0+9,n]),
//      k0 = k16*16 + 2*lr.
__device__ uint32_t g_A[(size_t)M_MAX * K_DIM / 2];
__device__ uint32_t g_B[(size_t)K_DIM * N_DIM / 2];
__device__ int      g_rowmod[K_DIM];              // (k*r3 + r1) % P
__device__ int      g_colmod[N_DIM];              // (n*r2) % P

__device__ __forceinline__ uint32_t pack_h2(float lo, float hi) {
    __half2 h = __floats2half2_rn(lo, hi);
    return *(uint32_t*)&h;
}
__device__ __forceinline__ uint32_t smem_u32(const void* p) {
    uint32_t a;
    asm("{ .reg .u64 t; cvta.to.shared.u64 t, %1; cvt.u32.u64 %0, t; }"
        : "=r"(a) : "l"(p));
    return a;
}
__device__ __forceinline__ void cp_async16(uint32_t dst, const void* src) {
    asm volatile("cp.async.cg.shared.global [%0], [%1], 16;"
                 :: "r"(dst), "l"(src) : "memory");
}
#define CP_COMMIT() asm volatile("cp.async.commit_group;" ::: "memory")
#define CP_WAIT1()  asm volatile("cp.async.wait_group 1;"  ::: "memory")
#define CP_WAIT0()  asm volatile("cp.async.wait_group 0;"  ::: "memory")

// m16n8k16 fp16 MMA, f32 accumulate (generic PTX, sm_80+)
__device__ __forceinline__ void mma_f16(float c[4], uint32_t a0, uint32_t a1,
                                        uint32_t a2, uint32_t a3,
                                        uint32_t b0, uint32_t b1) {
    asm volatile(
        "mma.sync.aligned.m16n8k16.row.col.f32.f16.f16.f32 "
        "{%0,%1,%2,%3}, {%4,%5,%6,%7}, {%8,%9}, {%0,%1,%2,%3};"
        : "+f"(c[0]), "+f"(c[1]), "+f"(c[2]), "+f"(c[3])
        : "r"(a0), "r"(a1), "r"(a2), "r"(a3), "r"(b0), "r"(b1));
}

// ============================================================================
// Kernel 1: hash residue tables (self-detects int64 vs int32 materialization)
// ============================================================================
__global__ void hash_tables_kernel(const void* __restrict__ rn_raw) {
    const long long* rn64 = (const long long*)rn_raw;
    const int*       rn32 = (const int*)rn_raw;
    long long r1, r2, r3;
    if (rn64[0] == P_CONST) { r1 = rn64[1]; r2 = rn64[2]; r3 = rn64[3]; }
    else                    { r1 = rn32[1]; r2 = rn32[2]; r3 = rn32[3]; }
    int i = blockIdx.x * blockDim.x + threadIdx.x;
    if (i < K_DIM) g_rowmod[i] = (int)(((long long)i * r3 + r1) % P_CONST);
    if (i < N_DIM) g_colmod[i] = (int)(((long long)i * r2) % P_CONST);
}

// ============================================================================
// Kernel 2 (fused prep): even blocks convert x -> fp16 fragment-major A;
// odd blocks gather W -> pair-major fp16 B. The two halves have different
// bottlenecks (DRAM streaming vs L2 random gather) and overlap when
// co-resident.
// ============================================================================
__global__ void prep_kernel(const float* __restrict__ x,
                            const float* __restrict__ hw,
                            int a_total, int g_total) {
    const int half_id = blockIdx.x >> 1;
    if ((blockIdx.x & 1) == 0) {
        // ---- cvt_a: fragment-major permutation ----
        int t = half_id * blockDim.x + threadIdx.x;
        if (t >= a_total) return;
        const int lane = t & 31;
        const int k16  = (t >> 5) & (K_DIM / 16 - 1);
        const int mt   = t >> (5 + 8);            // K/16 = 256 -> 8 bits
        const int lq = lane >> 2, lr = lane & 3;
        const float* xm = x + (size_t)(mt * 16) * K_DIM + k16 * 16;
        const float2 p0 = *(const float2*)(xm + (size_t)lq * K_DIM + 2 * lr);
        const float2 p1 = *(const float2*)(xm + (size_t)(lq + 8) * K_DIM + 2 * lr);
        const float2 p2 = *(const float2*)(xm + (size_t)lq * K_DIM + 2 * lr + 8);
        const float2 p3 = *(const float2*)(xm + (size_t)(lq + 8) * K_DIM + 2 * lr + 8);
        uint4 o;
        o.x = pack_h2(p0.x, p0.y);
        o.y = pack_h2(p1.x, p1.y);
        o.z = pack_h2(p2.x, p2.y);
        o.w = pack_h2(p3.x, p3.y);
        ((uint4*)g_A)[t] = o;
    } else {
        // ---- gather: W -> pair-major fp16 ----
        const int P = (int)P_CONST;
        int t = half_id * blockDim.x + threadIdx.x;
        if (t >= g_total) return;
        const int n  = t & (N_DIM - 1);
        const int r  = t >> 12;                     // k16*4 + lr
        const int lr = r & 3;
        const int k0 = (r >> 2) * 16 + 2 * lr;

        const int rm0 = g_rowmod[k0];
        const int rm1 = g_rowmod[k0 + 1];
        const int rm2 = g_rowmod[k0 + 8];
        const int rm3 = g_rowmod[k0 + 9];
        const int c   = g_colmod[n];

        int s0 = rm0 + c; if (s0 >= P) s0 -= P;
        int s1 = rm1 + c; if (s1 >= P) s1 -= P;
        int s2 = rm2 + c; if (s2 >= P) s2 -= P;
        int s3 = rm3 + c; if (s3 >= P) s3 -= P;

        const float w0 = __ldg(hw + (s0 & HASH_MASK));
        const float w1 = __ldg(hw + (s1 & HASH_MASK));
        const float w2 = __ldg(hw + (s2 & HASH_MASK));
        const float w3 = __ldg(hw + (s3 & HASH_MASK));

        uint2 o;
        o.x = pack_h2(w0, w1);
        o.y = pack_h2(w2, w3);
        ((uint2*)g_B)[t] = o;
    }
}

// ============================================================================
// Kernel 3: fp16 tensor-core GEMM via mma.sync m16n8k16
//   CTA tile 128x128, STAGE = 64 k (4 k16-steps), 256 thr (8 warps 2x4 ->
//   warp tile 64x32), 3-stage cp.async pipeline, ONE barrier per 64 k,
//   *** 2 CTAs per SM *** — when one CTA blocks at its barrier / cp-wait,
//   the other CTA's warps keep the tensor pipe fed (barrier decoupling
//   across independent CTAs; intra-CTA skew in R13 could not achieve this).
//   A fragments: 1x LDS.128 (fragment-major, conflict-free).
//   B fragments: 1x LDS.64 (pair-major, SB_W=264 ≡ 8 mod 32 words).
// ============================================================================
#define SB_W 264
#define A_STAGE_B (8 * 4 * 32 * 16)                // 16384 (8 mtiles x 4 ks)
#define B_STAGE_B (16 * SB_W * 4)                  // 16896 (16 rows)
#define STAGE_B   (A_STAGE_B + B_STAGE_B)          // 33280
#define NSTAGE 3
#define SMEM_GEMM (NSTAGE * STAGE_B)               // 99840 (x2 CTAs = 199680)
#define NK64      (K_DIM / 64)                     // 64 stages of work

__device__ __forceinline__ void load_stage(uint32_t sbase, int stage,
                                           int m0, int n0, int kt, int tid) {
    const uint32_t a_s = sbase + stage * STAGE_B;
    const uint32_t b_s = a_s + A_STAGE_B;
    // A: 32 fragment-chunks of 512B (i = mtile 0..7, j = ks 0..3);
    //    1024 x 16B transfers, 4 per thread; gmem chunk contiguous.
    #pragma unroll
    for (int p = 0; p < 4; p++) {
        const int u     = tid + p * 256;
        const int chunk = u >> 5;            // 0..31
        const int lane  = u & 31;
        const int i = chunk >> 2;            // mtile within CTA
        const int j = chunk & 3;             // ks
        const uint32_t* src = g_A +
            (((size_t)(m0 / 16 + i) * (K_DIM / 16) + (kt * 4 + j)) * 32
             + lane) * 4;
        cp_async16(a_s + u * 16, src);
    }
    // B: 16 rows x 256 words (64 x 16B chunks per row); 4 per thread.
    #pragma unroll
    for (int p = 0; p < 4; p++) {
        const int u = tid + p * 256;
        const int r = u >> 6;                // 0..15
        const int c = u & 63;
        const uint32_t* src =
            g_B + ((size_t)(kt * 16 + r) * N_DIM + n0) * 2 + c * 4;
        cp_async16(b_s + r * (SB_W * 4) + c * 16, src);
    }
}

__global__ __launch_bounds__(256, 2)
void gemm_mma_kernel(const float* __restrict__ bias, float* __restrict__ C) {
    extern __shared__ char smem[];
    const uint32_t sbase = smem_u32(smem);
    const int tid  = threadIdx.x;
    const int wid  = tid >> 5;
    const int lane = tid & 31;
    const int lq = lane >> 2;     // 0..7
    const int lr = lane & 3;      // 0..3
    const int wm = wid & 1;       // 2 m-halves of 64
    const int wn = wid >> 1;      // 4 n-slices of 32

    const int m_blk = blockIdx.y * 128;
    const int n_blk = blockIdx.x * 128;

    float acc[4][4][4];
    #pragma unroll
    for (int i = 0; i < 4; i++)
        #pragma unroll
        for (int j = 0; j < 4; j++)
            #pragma unroll
            for (int r = 0; r < 4; r++) acc[i][j][r] = 0.0f;

    load_stage(sbase, 0, m_blk, n_blk, 0, tid); CP_COMMIT();
    load_stage(sbase, 1, m_blk, n_blk, 1, tid); CP_COMMIT();

    int st = 0;
    for (int kt = 0; kt < NK64; kt++) {
        CP_WAIT1();
        __syncthreads();    // single barrier per 64 k: slot written at iter
                            // kt is (kt+2)%3 = (kt-1)%3, whose readers all
                            // passed this barrier already.
        const uint32_t* As = (const uint32_t*)(smem + st * STAGE_B);
        const uint32_t* Bs = (const uint32_t*)(smem + st * STAGE_B + A_STAGE_B);

        const uint32_t* a_base = As + (wm * 16) * 128 + lane * 4;
        const uint32_t* b_base = Bs + (wn * 32 + lq) * 2;

        #pragma unroll
        for (int ks = 0; ks < 4; ks++) {
            uint4 a[4];
            #pragma unroll
            for (int im = 0; im < 4; im++)
                a[im] = *(const uint4*)(a_base + (im * 4 + ks) * 128);
            uint2 b[4];
            #pragma unroll
            for (int jn = 0; jn < 4; jn++)
                b[jn] = *(const uint2*)
                    (b_base + (ks * 4 + lr) * SB_W + jn * 16);
            #pragma unroll
            for (int im = 0; im < 4; im++)
                #pragma unroll
                for (int jn = 0; jn < 4; jn++)
                    mma_f16(acc[im][jn], a[im].x, a[im].y, a[im].z, a[im].w,
                            b[jn].x, b[jn].y);
        }

        if (kt + 2 < NK64) {
            int ws = st + 2; if (ws >= NSTAGE) ws -= NSTAGE;
            load_stage(sbase, ws, m_blk, n_blk, kt + 2, tid);
        }
        CP_COMMIT();   // keep group count in lockstep even when empty
        st = (st == NSTAGE - 1) ? 0 : st + 1;
    }
    CP_WAIT0();

    // epilogue: bias + direct stores
    #pragma unroll
    for (int jn = 0; jn < 4; jn++) {
        const int c0 = n_blk + wn * 32 + jn * 8 + 2 * lr;
        const float bx = __ldg(bias + c0);
        const float by = __ldg(bias + c0 + 1);
        #pragma unroll
        for (int im = 0; im < 4; im++) {
            const int r0 = m_blk + wm * 64 + im * 16 + lq;
            float2 v0, v1;
            v0.x = acc[im][jn][0] + bx; v0.y = acc[im][jn][1] + by;
            v1.x = acc[im][jn][2] + bx; v1.y = acc[im][jn][3] + by;
            *(float2*)(C + (size_t)r0 * N_DIM + c0)       = v0;
            *(float2*)(C + (size_t)(r0 + 8) * N_DIM + c0) = v1;
        }
    }
}

// ============================================================================
// Host launch. Inputs routed by element count (immune to metadata ordering):
//   <=8 elems -> random_numbers; 2^20 -> hashed_weight; 4096 -> bias;
//   largest -> x. Output f32 [M, N_DIM].
// ============================================================================
extern "C" void kernel_launch(void* const* d_in, const int* in_sizes, int n_in,
                              void* d_out, int out_size) {
    const float* x = nullptr; const float* hw = nullptr;
    const void* rn = nullptr; const float* bias = nullptr;
    long long max_sz = -1; int max_i = 0;
    for (int i = 0; i < n_in; i++)
        if ((long long)in_sizes[i] > max_sz) { max_sz = in_sizes[i]; max_i = i; }
    x = (const float*)d_in[max_i];
    for (int i = 0; i < n_in; i++) {
        if (i == max_i) continue;
        if (in_sizes[i] <= 8)              rn   = d_in[i];
        else if (in_sizes[i] == (1 << 20)) hw   = (const float*)d_in[i];
        else if (in_sizes[i] == N_DIM)     bias = (const float*)d_in[i];
    }
    float* out = (float*)d_out;
    const int M = (int)(max_sz / K_DIM);   // 8192

    hash_tables_kernel<<<(K_DIM + 255) / 256, 256>>>(rn);

    const int a_total = (M / 16) * (K_DIM / 16) * 32;
    const int g_total = (K_DIM / 4) * N_DIM;
    const int a_blocks = (a_total + 255) / 256;
    const int g_blocks = (g_total + 255) / 256;
    const int mx_blocks = (a_blocks > g_blocks ? a_blocks : g_blocks);
    prep_kernel<<<2 * mx_blocks, 256>>>(x, hw, a_total, g_total);

    static bool smem_set = false;
    if (!smem_set) {
        cudaFuncSetAttribute(gemm_mma_kernel,
                             cudaFuncAttributeMaxDynamicSharedMemorySize,
                             SMEM_GEMM);
        smem_set = true;
    }
    dim3 grid(N_DIM / 128, M / 128);
    gemm_mma_kernel<<<grid, 256, SMEM_GEMM>>>(bias, out);
}